// round 6
// baseline (speedup 1.0000x reference)
#include <cuda_runtime.h>
#include <cuda_bf16.h>
#include <math.h>
#include <stdint.h>

// ---------------- scratch (device globals; no allocs allowed) ----------------
__device__ float g_z[512 * 448];            // z padded to 448 cols (cols 432..447 = 0)
__device__ float g_part[9 * 512 * 512];     // split-K partials
__device__ float g_h1[512 * 512];           // relu(inter@pw0+pb0)
// W0 transposed + converted: [n=512][k=186624] bf16, +32 pad elems (zero)
#define W0T_K 186624
__device__ __nv_bfloat16 g_w0t[512 * 186624 + 32];

// pack two fp32 -> bf16x2 (lo -> low half)
__device__ __forceinline__ uint32_t pack_bf16(float lo, float hi) {
    uint32_t r;
    asm("cvt.rn.bf16x2.f32 %0, %1, %2;" : "=r"(r) : "f"(hi), "f"(lo));
    return r;
}
__device__ __forceinline__ uint32_t smem_u32(const void* p) {
    uint32_t a;
    asm("{ .reg .u64 t; cvta.to.shared.u64 t, %1; cvt.u32.u64 %0, t; }" : "=r"(a) : "l"(p));
    return a;
}
#define LDSM4(R0, R1, R2, R3, ADDR)                                            \
    asm volatile("ldmatrix.sync.aligned.m8n8.x4.shared.b16 {%0,%1,%2,%3}, [%4];" \
                 : "=r"(R0), "=r"(R1), "=r"(R2), "=r"(R3) : "r"(ADDR))
__device__ __forceinline__ void cpasync32(uint32_t dst, const void* src) {
    asm volatile(
        "cp.async.cg.shared.global [%0], [%1], 16;\n\t"
        "cp.async.cg.shared.global [%2], [%3], 16;"
        :: "r"(dst), "l"(src), "r"(dst + 16), "l"((const char*)src + 16) : "memory");
}
#define CP_COMMIT() asm volatile("cp.async.commit_group;" ::: "memory")
#define CP_WAIT2()  asm volatile("cp.async.wait_group 2;" ::: "memory")

// ---------------- kernel 0: convert + transpose W0 -> bf16 [n][k] ----------
__global__ void convert_w0_kernel(const float* __restrict__ W0) {
    __shared__ float s[64][65];
    const int kb = blockIdx.x * 64, nb = blockIdx.y * 64;
    const int t = threadIdx.x;
    const int kr = t >> 4, nq = t & 15;
    #pragma unroll
    for (int r = 0; r < 4; r++) {
        int k = kr + r * 16;
        float4 v = *(const float4*)(W0 + (size_t)(kb + k) * 512 + nb + nq * 4);
        s[k][nq * 4] = v.x; s[k][nq * 4 + 1] = v.y;
        s[k][nq * 4 + 2] = v.z; s[k][nq * 4 + 3] = v.w;
    }
    __syncthreads();
    const int nr = t >> 4, kq = t & 15;
    #pragma unroll
    for (int r = 0; r < 4; r++) {
        int n = nr + r * 16;
        uint32_t lo = pack_bf16(s[kq * 4][n],     s[kq * 4 + 1][n]);
        uint32_t hi = pack_bf16(s[kq * 4 + 2][n], s[kq * 4 + 3][n]);
        *(uint2*)(g_w0t + (size_t)(nb + n) * W0T_K + kb + kq * 4) = make_uint2(lo, hi);
    }
    if (blockIdx.x == 0 && blockIdx.y == 0 && t < 32)
        g_w0t[(size_t)512 * W0T_K + t] = __float2bfloat16(0.f);  // zero pad tail
}

// ---------------- kernel 1: dense MLP (4 batch rows / block) ----------------
__global__ void dense_mlp_kernel(const float* __restrict__ x,
                                 const float* __restrict__ dw0, const float* __restrict__ db0,
                                 const float* __restrict__ dw1, const float* __restrict__ db1,
                                 const float* __restrict__ dw2, const float* __restrict__ db2,
                                 const float* __restrict__ dw3, const float* __restrict__ db3) {
    __shared__ float xs[4][13];
    __shared__ float h0[4][512];
    __shared__ float h1[4][256];
    __shared__ float h2[4][64];
    const int r0 = blockIdx.x * 4;
    const int tid = threadIdx.x;

    if (tid < 52) xs[tid / 13][tid % 13] = x[(r0 + tid / 13) * 13 + tid % 13];
    __syncthreads();

    #pragma unroll
    for (int jj = 0; jj < 2; jj++) {
        int j = tid + jj * 256;
        float a[4];
        float b = db0[j];
        #pragma unroll
        for (int r = 0; r < 4; r++) a[r] = b;
        #pragma unroll
        for (int i = 0; i < 13; i++) {
            float w = dw0[i * 512 + j];
            #pragma unroll
            for (int r = 0; r < 4; r++) a[r] += xs[r][i] * w;
        }
        #pragma unroll
        for (int r = 0; r < 4; r++) h0[r][j] = fmaxf(a[r], 0.f);
    }
    __syncthreads();

    {
        float a[4];
        float b = db1[tid];
        #pragma unroll
        for (int r = 0; r < 4; r++) a[r] = b;
        #pragma unroll 8
        for (int i = 0; i < 512; i++) {
            float w = dw1[i * 256 + tid];
            #pragma unroll
            for (int r = 0; r < 4; r++) a[r] += h0[r][i] * w;
        }
        #pragma unroll
        for (int r = 0; r < 4; r++) h1[r][tid] = fmaxf(a[r], 0.f);
    }
    __syncthreads();

    if (tid < 64) {
        float a[4];
        float b = db2[tid];
        #pragma unroll
        for (int r = 0; r < 4; r++) a[r] = b;
        #pragma unroll 8
        for (int i = 0; i < 256; i++) {
            float w = dw2[i * 64 + tid];
            #pragma unroll
            for (int r = 0; r < 4; r++) a[r] += h1[r][i] * w;
        }
        #pragma unroll
        for (int r = 0; r < 4; r++) h2[r][tid] = fmaxf(a[r], 0.f);
    }
    __syncthreads();

    if (tid < 16) {
        float a[4];
        float b = db3[tid];
        #pragma unroll
        for (int r = 0; r < 4; r++) a[r] = b;
        #pragma unroll
        for (int i = 0; i < 64; i++) {
            float w = dw3[i * 16 + tid];
            #pragma unroll
            for (int r = 0; r < 4; r++) a[r] += h2[r][i] * w;
        }
        #pragma unroll
        for (int r = 0; r < 4; r++) g_z[(size_t)(r0 + r) * 448 + tid] = a[r];
    }
    if (tid >= 64 && tid < 128) {
        int u = tid - 64;
        g_z[(size_t)(r0 + u / 16) * 448 + 432 + (u % 16)] = 0.f;
    }
}

// ---------------- kernel 2: embedding gather -> z[:,16:432] ----------------
__global__ void embed_kernel(const void* __restrict__ sp, const float* __restrict__ emb) {
    int t = blockIdx.x * blockDim.x + threadIdx.x;
    if (t >= 512 * 26) return;
    const int* si = (const int*)sp;
    bool is64 = (si[1] == 0 && si[3] == 0 && si[5] == 0);
    long long v = is64 ? ((const long long*)sp)[t] : (long long)si[t];
    int id = (int)((v + 1) % 100000);
    int b = t / 26, f = t - b * 26;
    const float4* src = (const float4*)(emb + ((size_t)f * 100000 + id) * 16);
    float4* dst = (float4*)(g_z + (size_t)b * 448 + 16 + f * 16);
    dst[0] = src[0]; dst[1] = src[1]; dst[2] = src[2]; dst[3] = src[3];
}

// ---------------- kernel 3: interaction GEMM (bf16 mma + cp.async + ldsm) ---
// C[512,512] = A @ W0, A[b, p*432+q] = z[b,p]*z[b,q]
// CTA: 128m x 128n, 48 p per split (9 splits). Stage = 32 k (one q-window for one p).
// A tile [128m][32k] bf16 pitch 80B (built in smem from z products, double buffered)
// B tile [128n][32k] bf16 pitch 80B (cp.async from g_w0t, 4-stage ring)
#define GOFF_ZQ 0u            // [128][36] f32 = 18432
#define GOFF_ZP 18432u        // [128][49] f32 = 25088
#define GOFF_A  43520u        // 2 x 10240
#define GOFF_B  64000u        // 4 x 10240
#define GSMEM   104960u

__global__ __launch_bounds__(256) void inter_gemm_kernel() {
    extern __shared__ char smem[];
    const uint32_t sb = smem_u32(smem);
    float* zq_s = (float*)(smem + GOFF_ZQ);   // row pitch 144B (36 floats)
    float* zp_s = (float*)(smem + GOFF_ZP);   // row pitch 49 floats

    const int tid = threadIdx.x;
    const int warp = tid >> 5, lane = tid & 31;
    const int m0 = blockIdx.x * 128;          // m fastest -> L2 dedupe of W0t stream
    const int n0 = blockIdx.y * 128;
    const int p0 = blockIdx.z * 48;
    const int wm0 = (warp >> 2) * 64, wn0 = (warp & 3) * 32;

    // ---- load zp [128][48] ----
    for (int i = tid; i < 128 * 48; i += 256) {
        int b = i / 48, j = i - b * 48;
        zp_s[b * 49 + j] = g_z[(size_t)(m0 + b) * 448 + p0 + j];
    }
    // ---- load zq window 0 ----
    for (int i = tid; i < 1024; i += 256) {
        int m = i >> 3, kq = i & 7;
        float4 v = *(const float4*)(g_z + (size_t)(m0 + m) * 448 + kq * 4);
        *(float4*)((char*)zq_s + m * 144 + kq * 16) = v;
    }
    __syncthreads();

    // ---- A staging params ----
    const int am = tid & 127, ah = tid >> 7;  // row, k-half (16 k each)
    // ---- B cp.async params: thread -> (n row, 32B k-half) ----
    const int bn = tid >> 1;
    const int bko = (tid & 1) * 16;           // element offset (16 elems = 32B)
    const __nv_bfloat16* wrow = g_w0t + (size_t)(n0 + bn) * W0T_K;
    const uint32_t bdst_base = sb + GOFF_B + (uint32_t)(bn * 80 + bko * 2);

#define STAGE_A(P, BUF) do {                                                   \
        float vp = zp_s[am * 49 + (P)];                                        \
        const float4* q4 = (const float4*)((char*)zq_s + am * 144 + ah * 64);  \
        uint32_t w_[8];                                                        \
        _Pragma("unroll")                                                      \
        for (int i_ = 0; i_ < 4; i_++) {                                       \
            float4 v_ = q4[i_];                                                \
            w_[2 * i_]     = pack_bf16(vp * v_.x, vp * v_.y);                  \
            w_[2 * i_ + 1] = pack_bf16(vp * v_.z, vp * v_.w);                  \
        }                                                                      \
        char* ab_ = smem + GOFF_A + (BUF) * 10240 + am * 80 + ah * 32;         \
        *(uint4*)ab_        = make_uint4(w_[0], w_[1], w_[2], w_[3]);          \
        *(uint4*)(ab_ + 16) = make_uint4(w_[4], w_[5], w_[6], w_[7]);          \
    } while (0)

#define ISSUE_B(ST) do {                                                       \
        int qc_ = (ST) / 48, pp_ = (ST) - qc_ * 48;                            \
        size_t k0_ = (size_t)(p0 + pp_) * 432 + qc_ * 32 + bko;                \
        cpasync32(bdst_base + ((ST) & 3) * 10240u, wrow + k0_);                \
    } while (0)

    // ---- prologue: A[0] + B stages 0..2 ----
    STAGE_A(0, 0);
    ISSUE_B(0); CP_COMMIT();
    ISSUE_B(1); CP_COMMIT();
    ISSUE_B(2); CP_COMMIT();

    float acc[4][4][4];
    #pragma unroll
    for (int mi = 0; mi < 4; mi++)
        #pragma unroll
        for (int nj = 0; nj < 4; nj++)
            #pragma unroll
            for (int k = 0; k < 4; k++) acc[mi][nj][k] = 0.f;

    const uint32_t a_lrow = (uint32_t)((lane & 15) * 80 + ((lane >> 4) & 1) * 16);
    const uint32_t b_lrow = (uint32_t)((((lane >> 4) & 1) * 8 + (lane & 7)) * 80 + ((lane >> 3) & 1) * 16);

    for (int s = 0; s < 672; s++) {
        CP_WAIT2();
        __syncthreads();                       // B[s] visible; prior buffers free
        if (s + 3 < 672) ISSUE_B(s + 3);
        CP_COMMIT();

        const uint32_t A_base = sb + GOFF_A + (uint32_t)((s & 1) * 10240);
        const uint32_t B_base = sb + GOFF_B + (uint32_t)((s & 3) * 10240);

        uint32_t af[2][4][4], bfr[2][2][4];
        #pragma unroll
        for (int ks = 0; ks < 2; ks++) {
            #pragma unroll
            for (int mi = 0; mi < 4; mi++) {
                uint32_t addr = A_base + (uint32_t)((wm0 + mi * 16) * 80 + ks * 32) + a_lrow;
                LDSM4(af[ks][mi][0], af[ks][mi][1], af[ks][mi][2], af[ks][mi][3], addr);
            }
            #pragma unroll
            for (int njp = 0; njp < 2; njp++) {
                uint32_t addr = B_base + (uint32_t)((wn0 + njp * 16) * 80 + ks * 32) + b_lrow;
                LDSM4(bfr[ks][njp][0], bfr[ks][njp][1], bfr[ks][njp][2], bfr[ks][njp][3], addr);
            }
        }

        // stage A[s+1] (independent of MMAs below; overlaps)
        if (s + 1 < 672) {
            if (((s + 1) & 47) == ((s + 1) % 48) && ((s + 1) % 48) == 0) { }
            if (((s + 1) % 48) == 0) {
                int w = (s + 1) / 48;
                __syncthreads();               // zq readers (A[s] staging) done
                for (int i = tid; i < 1024; i += 256) {
                    int m = i >> 3, kq = i & 7;
                    float4 v = *(const float4*)(g_z + (size_t)(m0 + m) * 448 + w * 32 + kq * 4);
                    *(float4*)((char*)zq_s + m * 144 + kq * 16) = v;
                }
                __syncthreads();
            }
            STAGE_A((s + 1) % 48, (s + 1) & 1);
        }

        #pragma unroll
        for (int ks = 0; ks < 2; ks++)
            #pragma unroll
            for (int mi = 0; mi < 4; mi++)
                #pragma unroll
                for (int nj = 0; nj < 4; nj++) {
                    uint32_t b0 = bfr[ks][nj >> 1][(nj & 1) * 2];
                    uint32_t b1 = bfr[ks][nj >> 1][(nj & 1) * 2 + 1];
                    asm volatile(
                        "mma.sync.aligned.m16n8k16.row.col.f32.bf16.bf16.f32 "
                        "{%0,%1,%2,%3},{%4,%5,%6,%7},{%8,%9},{%0,%1,%2,%3};"
                        : "+f"(acc[mi][nj][0]), "+f"(acc[mi][nj][1]),
                          "+f"(acc[mi][nj][2]), "+f"(acc[mi][nj][3])
                        : "r"(af[ks][mi][0]), "r"(af[ks][mi][1]),
                          "r"(af[ks][mi][2]), "r"(af[ks][mi][3]),
                          "r"(b0), "r"(b1));
                }
    }

    // epilogue: write split partials
    const int g = lane >> 2, c = lane & 3;
    #pragma unroll
    for (int mi = 0; mi < 4; mi++)
        #pragma unroll
        for (int nj = 0; nj < 4; nj++) {
            int row = m0 + wm0 + 16 * mi + g;
            int col = n0 + wn0 + 8 * nj + 2 * c;
            float* d0 = g_part + ((size_t)blockIdx.z * 512 + row) * 512 + col;
            float* d1 = g_part + ((size_t)blockIdx.z * 512 + row + 8) * 512 + col;
            *(float2*)d0 = make_float2(acc[mi][nj][0], acc[mi][nj][1]);
            *(float2*)d1 = make_float2(acc[mi][nj][2], acc[mi][nj][3]);
        }
}
#undef STAGE_A
#undef ISSUE_B

// ---------------- kernel 4: reduce split-K partials + bias + relu ----------
__global__ void reduce_relu_kernel(const float* __restrict__ pb0) {
    int b = blockIdx.x;
    for (int j = threadIdx.x; j < 512; j += 256) {
        float s = pb0[j];
        #pragma unroll
        for (int sp = 0; sp < 9; sp++)
            s += g_part[((size_t)sp * 512 + b) * 512 + j];
        g_h1[(size_t)b * 512 + j] = fmaxf(s, 0.f);
    }
}

// ---------------- kernel 5: prediction MLP + sigmoid -----------------------
__global__ void pred_kernel(const float* __restrict__ pw1, const float* __restrict__ pb1,
                            const float* __restrict__ pw2, const float* __restrict__ pb2,
                            float* __restrict__ out) {
    __shared__ float h1s[4][512];
    __shared__ float h2s[4][256];
    __shared__ float red[4][8];
    const int r0 = blockIdx.x * 4;
    const int tid = threadIdx.x;

    for (int i = tid; i < 2048; i += 256)
        h1s[i >> 9][i & 511] = g_h1[(size_t)(r0 + (i >> 9)) * 512 + (i & 511)];
    __syncthreads();

    {
        float a[4];
        float b = pb1[tid];
        #pragma unroll
        for (int r = 0; r < 4; r++) a[r] = b;
        #pragma unroll 8
        for (int i = 0; i < 512; i++) {
            float w = pw1[i * 256 + tid];
            #pragma unroll
            for (int r = 0; r < 4; r++) a[r] += h1s[r][i] * w;
        }
        #pragma unroll
        for (int r = 0; r < 4; r++) h2s[r][tid] = fmaxf(a[r], 0.f);
    }
    __syncthreads();

    float w2 = pw2[tid];
    int lane = tid & 31, wp = tid >> 5;
    #pragma unroll
    for (int r = 0; r < 4; r++) {
        float v = h2s[r][tid] * w2;
        #pragma unroll
        for (int o = 16; o; o >>= 1) v += __shfl_xor_sync(0xffffffffu, v, o);
        if (lane == 0) red[r][wp] = v;
    }
    __syncthreads();
    if (tid < 4) {
        float s = pb2[0];
        #pragma unroll
        for (int w = 0; w < 8; w++) s += red[tid][w];
        out[r0 + tid] = 1.f / (1.f + expf(-s));
    }
}

// ---------------- launch ----------------------------------------------------
extern "C" void kernel_launch(void* const* d_in, const int* in_sizes, int n_in,
                              void* d_out, int out_size) {
    const float* x   = (const float*)d_in[0];
    const void*  sp  = d_in[1];
    const float* emb = (const float*)d_in[2];
    const float* dw0 = (const float*)d_in[3];
    const float* db0 = (const float*)d_in[4];
    const float* dw1 = (const float*)d_in[5];
    const float* db1 = (const float*)d_in[6];
    const float* dw2 = (const float*)d_in[7];
    const float* db2 = (const float*)d_in[8];
    const float* dw3 = (const float*)d_in[9];
    const float* db3 = (const float*)d_in[10];
    const float* pw0 = (const float*)d_in[11];
    const float* pb0 = (const float*)d_in[12];
    const float* pw1 = (const float*)d_in[13];
    const float* pb1 = (const float*)d_in[14];
    const float* pw2 = (const float*)d_in[15];
    const float* pb2 = (const float*)d_in[16];
    float* out = (float*)d_out;

    cudaFuncSetAttribute(inter_gemm_kernel,
                         cudaFuncAttributeMaxDynamicSharedMemorySize, (int)GSMEM);

    convert_w0_kernel<<<dim3(186624 / 64, 8), 256>>>(pw0);
    dense_mlp_kernel<<<128, 256>>>(x, dw0, db0, dw1, db1, dw2, db2, dw3, db3);
    embed_kernel<<<52, 256>>>(sp, emb);
    inter_gemm_kernel<<<dim3(4, 4, 9), 256, GSMEM>>>();
    reduce_relu_kernel<<<512, 256>>>(pb0);
    pred_kernel<<<128, 256>>>(pw1, pb1, pw2, pb2, out);
}

// round 7
// speedup vs baseline: 1.2721x; 1.2721x over previous
#include <cuda_runtime.h>
#include <cuda_bf16.h>
#include <math.h>
#include <stdint.h>

// ---------------- scratch (device globals; no allocs allowed) ----------------
__device__ float g_z[512 * 448];            // z padded to 448 cols (cols 432..447 = 0)
__device__ float g_part[18 * 512 * 512];    // split-K partials
__device__ float g_h1[512 * 512];           // relu(inter@pw0+pb0)
// W0 transposed + converted: [n=512][k=186624] bf16, +32 pad elems (zero)
#define W0T_K 186624
__device__ __nv_bfloat16 g_w0t[512 * 186624 + 32];

// pack two fp32 -> bf16x2 (lo -> low half)
__device__ __forceinline__ uint32_t pack_bf16(float lo, float hi) {
    uint32_t r;
    asm("cvt.rn.bf16x2.f32 %0, %1, %2;" : "=r"(r) : "f"(hi), "f"(lo));
    return r;
}
__device__ __forceinline__ uint32_t smem_u32(const void* p) {
    uint32_t a;
    asm("{ .reg .u64 t; cvta.to.shared.u64 t, %1; cvt.u32.u64 %0, t; }" : "=r"(a) : "l"(p));
    return a;
}
#define LDSM4(R0, R1, R2, R3, ADDR)                                            \
    asm volatile("ldmatrix.sync.aligned.m8n8.x4.shared.b16 {%0,%1,%2,%3}, [%4];" \
                 : "=r"(R0), "=r"(R1), "=r"(R2), "=r"(R3) : "r"(ADDR))
__device__ __forceinline__ void cpasync32(uint32_t dst, const void* src) {
    asm volatile(
        "cp.async.cg.shared.global [%0], [%1], 16;\n\t"
        "cp.async.cg.shared.global [%2], [%3], 16;"
        :: "r"(dst), "l"(src), "r"(dst + 16), "l"((const char*)src + 16) : "memory");
}
#define CP_COMMIT() asm volatile("cp.async.commit_group;" ::: "memory")
#define CP_WAIT2()  asm volatile("cp.async.wait_group 2;" ::: "memory")

// ---------------- kernel 0: convert + transpose W0 -> bf16 [n][k] ----------
__global__ void convert_w0_kernel(const float* __restrict__ W0) {
    __shared__ float s[64][65];
    const int kb = blockIdx.x * 64, nb = blockIdx.y * 64;
    const int t = threadIdx.x;
    const int kr = t >> 4, nq = t & 15;
    #pragma unroll
    for (int r = 0; r < 4; r++) {
        int k = kr + r * 16;
        float4 v = *(const float4*)(W0 + (size_t)(kb + k) * 512 + nb + nq * 4);
        s[k][nq * 4] = v.x; s[k][nq * 4 + 1] = v.y;
        s[k][nq * 4 + 2] = v.z; s[k][nq * 4 + 3] = v.w;
    }
    __syncthreads();
    const int nr = t >> 4, kq = t & 15;
    #pragma unroll
    for (int r = 0; r < 4; r++) {
        int n = nr + r * 16;
        uint32_t lo = pack_bf16(s[kq * 4][n],     s[kq * 4 + 1][n]);
        uint32_t hi = pack_bf16(s[kq * 4 + 2][n], s[kq * 4 + 3][n]);
        *(uint2*)(g_w0t + (size_t)(nb + n) * W0T_K + kb + kq * 4) = make_uint2(lo, hi);
    }
    if (blockIdx.x == 0 && blockIdx.y == 0 && t < 32)
        g_w0t[(size_t)512 * W0T_K + t] = __float2bfloat16(0.f);  // zero pad tail
}

// ---------------- kernel 1: dense MLP (4 batch rows / block) ----------------
__global__ void dense_mlp_kernel(const float* __restrict__ x,
                                 const float* __restrict__ dw0, const float* __restrict__ db0,
                                 const float* __restrict__ dw1, const float* __restrict__ db1,
                                 const float* __restrict__ dw2, const float* __restrict__ db2,
                                 const float* __restrict__ dw3, const float* __restrict__ db3) {
    __shared__ float xs[4][13];
    __shared__ float h0[4][512];
    __shared__ float h1[4][256];
    __shared__ float h2[4][64];
    const int r0 = blockIdx.x * 4;
    const int tid = threadIdx.x;

    if (tid < 52) xs[tid / 13][tid % 13] = x[(r0 + tid / 13) * 13 + tid % 13];
    __syncthreads();

    #pragma unroll
    for (int jj = 0; jj < 2; jj++) {
        int j = tid + jj * 256;
        float a[4];
        float b = db0[j];
        #pragma unroll
        for (int r = 0; r < 4; r++) a[r] = b;
        #pragma unroll
        for (int i = 0; i < 13; i++) {
            float w = dw0[i * 512 + j];
            #pragma unroll
            for (int r = 0; r < 4; r++) a[r] += xs[r][i] * w;
        }
        #pragma unroll
        for (int r = 0; r < 4; r++) h0[r][j] = fmaxf(a[r], 0.f);
    }
    __syncthreads();

    {
        float a[4];
        float b = db1[tid];
        #pragma unroll
        for (int r = 0; r < 4; r++) a[r] = b;
        #pragma unroll 8
        for (int i = 0; i < 512; i++) {
            float w = dw1[i * 256 + tid];
            #pragma unroll
            for (int r = 0; r < 4; r++) a[r] += h0[r][i] * w;
        }
        #pragma unroll
        for (int r = 0; r < 4; r++) h1[r][tid] = fmaxf(a[r], 0.f);
    }
    __syncthreads();

    if (tid < 64) {
        float a[4];
        float b = db2[tid];
        #pragma unroll
        for (int r = 0; r < 4; r++) a[r] = b;
        #pragma unroll 8
        for (int i = 0; i < 256; i++) {
            float w = dw2[i * 64 + tid];
            #pragma unroll
            for (int r = 0; r < 4; r++) a[r] += h1[r][i] * w;
        }
        #pragma unroll
        for (int r = 0; r < 4; r++) h2[r][tid] = fmaxf(a[r], 0.f);
    }
    __syncthreads();

    if (tid < 16) {
        float a[4];
        float b = db3[tid];
        #pragma unroll
        for (int r = 0; r < 4; r++) a[r] = b;
        #pragma unroll
        for (int i = 0; i < 64; i++) {
            float w = dw3[i * 16 + tid];
            #pragma unroll
            for (int r = 0; r < 4; r++) a[r] += h2[r][i] * w;
        }
        #pragma unroll
        for (int r = 0; r < 4; r++) g_z[(size_t)(r0 + r) * 448 + tid] = a[r];
    }
    if (tid >= 64 && tid < 128) {
        int u = tid - 64;
        g_z[(size_t)(r0 + u / 16) * 448 + 432 + (u % 16)] = 0.f;
    }
}

// ---------------- kernel 2: embedding gather -> z[:,16:432] ----------------
__global__ void embed_kernel(const void* __restrict__ sp, const float* __restrict__ emb) {
    int t = blockIdx.x * blockDim.x + threadIdx.x;
    if (t >= 512 * 26) return;
    const int* si = (const int*)sp;
    bool is64 = (si[1] == 0 && si[3] == 0 && si[5] == 0);
    long long v = is64 ? ((const long long*)sp)[t] : (long long)si[t];
    int id = (int)((v + 1) % 100000);
    int b = t / 26, f = t - b * 26;
    const float4* src = (const float4*)(emb + ((size_t)f * 100000 + id) * 16);
    float4* dst = (float4*)(g_z + (size_t)b * 448 + 16 + f * 16);
    dst[0] = src[0]; dst[1] = src[1]; dst[2] = src[2]; dst[3] = src[3];
}

// ---------------- kernel 3: interaction GEMM (bf16 mma + cp.async + ldsm) ---
// C[512,512] = A @ W0, A[b, p*432+q] = z[b,p]*z[b,q]
// CTA: 128m x 128n, 24 p per split (18 splits -> 288 CTAs = 2 per SM).
// Stage = 32 k (one q-window chunk for one p). 14 windows * 24 p = 336 stages.
// A tile [128m][32k] bf16 pitch 80B (built in smem from z products, x2 buf)
// B tile [128n][32k] bf16 pitch 80B (cp.async from g_w0t, 4-stage ring)
#define GOFF_ZQ 0u            // [128][36] f32 = 18432
#define GOFF_ZP 18432u        // [128][25] f32 = 12800
#define GOFF_A  31232u        // 2 x 10240
#define GOFF_B  51712u        // 4 x 10240
#define GSMEM   92672u

__global__ __launch_bounds__(256, 2) void inter_gemm_kernel() {
    extern __shared__ char smem[];
    const uint32_t sb = smem_u32(smem);
    float* zq_s = (float*)(smem + GOFF_ZQ);   // row pitch 144B (36 floats)
    float* zp_s = (float*)(smem + GOFF_ZP);   // row pitch 25 floats

    const int tid = threadIdx.x;
    const int warp = tid >> 5, lane = tid & 31;
    const int m0 = blockIdx.x * 128;          // m fastest -> L2 dedupe of W0t stream
    const int n0 = blockIdx.y * 128;
    const int p0 = blockIdx.z * 24;
    const int wm0 = (warp >> 2) * 64, wn0 = (warp & 3) * 32;

    // ---- load zp [128][24] ----
    for (int i = tid; i < 128 * 24; i += 256) {
        int b = i / 24, j = i - b * 24;
        zp_s[b * 25 + j] = g_z[(size_t)(m0 + b) * 448 + p0 + j];
    }
    // ---- load zq window 0 ----
    for (int i = tid; i < 1024; i += 256) {
        int m = i >> 3, kq = i & 7;
        float4 v = *(const float4*)(g_z + (size_t)(m0 + m) * 448 + kq * 4);
        *(float4*)((char*)zq_s + m * 144 + kq * 16) = v;
    }
    __syncthreads();

    // ---- A staging params ----
    const int am = tid & 127, ah = tid >> 7;  // row, k-half (16 k each)
    // ---- B cp.async params: thread -> (n row, 32B k-half) ----
    const int bn = tid >> 1;
    const int bko = (tid & 1) * 16;           // element offset (16 elems = 32B)
    const __nv_bfloat16* wrow = g_w0t + (size_t)(n0 + bn) * W0T_K;
    const uint32_t bdst_base = sb + GOFF_B + (uint32_t)(bn * 80 + bko * 2);

#define STAGE_A(P, BUF) do {                                                   \
        float vp = zp_s[am * 25 + (P)];                                        \
        const float4* q4 = (const float4*)((char*)zq_s + am * 144 + ah * 64);  \
        uint32_t w_[8];                                                        \
        _Pragma("unroll")                                                      \
        for (int i_ = 0; i_ < 4; i_++) {                                       \
            float4 v_ = q4[i_];                                                \
            w_[2 * i_]     = pack_bf16(vp * v_.x, vp * v_.y);                  \
            w_[2 * i_ + 1] = pack_bf16(vp * v_.z, vp * v_.w);                  \
        }                                                                      \
        char* ab_ = smem + GOFF_A + (BUF) * 10240 + am * 80 + ah * 32;         \
        *(uint4*)ab_        = make_uint4(w_[0], w_[1], w_[2], w_[3]);          \
        *(uint4*)(ab_ + 16) = make_uint4(w_[4], w_[5], w_[6], w_[7]);          \
    } while (0)

#define ISSUE_B(ST) do {                                                       \
        int qc_ = (ST) / 24, pp_ = (ST) - qc_ * 24;                            \
        size_t k0_ = (size_t)(p0 + pp_) * 432 + qc_ * 32 + bko;                \
        cpasync32(bdst_base + ((ST) & 3) * 10240u, wrow + k0_);                \
    } while (0)

    // ---- prologue: A[0] + B stages 0..2 ----
    STAGE_A(0, 0);
    ISSUE_B(0); CP_COMMIT();
    ISSUE_B(1); CP_COMMIT();
    ISSUE_B(2); CP_COMMIT();

    float acc[4][4][4];
    #pragma unroll
    for (int mi = 0; mi < 4; mi++)
        #pragma unroll
        for (int nj = 0; nj < 4; nj++)
            #pragma unroll
            for (int k = 0; k < 4; k++) acc[mi][nj][k] = 0.f;

    const uint32_t a_lrow = (uint32_t)((lane & 15) * 80 + ((lane >> 4) & 1) * 16);
    const uint32_t b_lrow = (uint32_t)((((lane >> 4) & 1) * 8 + (lane & 7)) * 80 + ((lane >> 3) & 1) * 16);

    for (int s = 0; s < 336; s++) {
        CP_WAIT2();
        __syncthreads();                       // B[s] visible; prior buffers free
        if (s + 3 < 336) ISSUE_B(s + 3);
        CP_COMMIT();

        const uint32_t A_base = sb + GOFF_A + (uint32_t)((s & 1) * 10240);
        const uint32_t B_base = sb + GOFF_B + (uint32_t)((s & 3) * 10240);

        // ---- k-step 0: load frags, then (overlap) stage A[s+1], then MMA ----
        uint32_t af[4][4], bfr[2][4];
        #pragma unroll
        for (int mi = 0; mi < 4; mi++)
            LDSM4(af[mi][0], af[mi][1], af[mi][2], af[mi][3],
                  A_base + (uint32_t)((wm0 + mi * 16) * 80) + a_lrow);
        #pragma unroll
        for (int njp = 0; njp < 2; njp++)
            LDSM4(bfr[njp][0], bfr[njp][1], bfr[njp][2], bfr[njp][3],
                  B_base + (uint32_t)((wn0 + njp * 16) * 80) + b_lrow);

        if (s + 1 < 336) {
            if (((s + 1) % 24) == 0) {
                int w = (s + 1) / 24;
                __syncthreads();               // all warps done reading old zq
                for (int i = tid; i < 1024; i += 256) {
                    int m = i >> 3, kq = i & 7;
                    float4 v = *(const float4*)(g_z + (size_t)(m0 + m) * 448 + w * 32 + kq * 4);
                    *(float4*)((char*)zq_s + m * 144 + kq * 16) = v;
                }
                __syncthreads();
            }
            STAGE_A((s + 1) % 24, (s + 1) & 1);
        }

        #pragma unroll
        for (int mi = 0; mi < 4; mi++)
            #pragma unroll
            for (int nj = 0; nj < 4; nj++) {
                uint32_t b0 = bfr[nj >> 1][(nj & 1) * 2];
                uint32_t b1 = bfr[nj >> 1][(nj & 1) * 2 + 1];
                asm volatile(
                    "mma.sync.aligned.m16n8k16.row.col.f32.bf16.bf16.f32 "
                    "{%0,%1,%2,%3},{%4,%5,%6,%7},{%8,%9},{%0,%1,%2,%3};"
                    : "+f"(acc[mi][nj][0]), "+f"(acc[mi][nj][1]),
                      "+f"(acc[mi][nj][2]), "+f"(acc[mi][nj][3])
                    : "r"(af[mi][0]), "r"(af[mi][1]), "r"(af[mi][2]), "r"(af[mi][3]),
                      "r"(b0), "r"(b1));
            }

        // ---- k-step 1 ----
        #pragma unroll
        for (int mi = 0; mi < 4; mi++)
            LDSM4(af[mi][0], af[mi][1], af[mi][2], af[mi][3],
                  A_base + (uint32_t)((wm0 + mi * 16) * 80 + 32) + a_lrow);
        #pragma unroll
        for (int njp = 0; njp < 2; njp++)
            LDSM4(bfr[njp][0], bfr[njp][1], bfr[njp][2], bfr[njp][3],
                  B_base + (uint32_t)((wn0 + njp * 16) * 80 + 32) + b_lrow);

        #pragma unroll
        for (int mi = 0; mi < 4; mi++)
            #pragma unroll
            for (int nj = 0; nj < 4; nj++) {
                uint32_t b0 = bfr[nj >> 1][(nj & 1) * 2];
                uint32_t b1 = bfr[nj >> 1][(nj & 1) * 2 + 1];
                asm volatile(
                    "mma.sync.aligned.m16n8k16.row.col.f32.bf16.bf16.f32 "
                    "{%0,%1,%2,%3},{%4,%5,%6,%7},{%8,%9},{%0,%1,%2,%3};"
                    : "+f"(acc[mi][nj][0]), "+f"(acc[mi][nj][1]),
                      "+f"(acc[mi][nj][2]), "+f"(acc[mi][nj][3])
                    : "r"(af[mi][0]), "r"(af[mi][1]), "r"(af[mi][2]), "r"(af[mi][3]),
                      "r"(b0), "r"(b1));
            }
    }

    // epilogue: write split partials
    const int g = lane >> 2, c = lane & 3;
    #pragma unroll
    for (int mi = 0; mi < 4; mi++)
        #pragma unroll
        for (int nj = 0; nj < 4; nj++) {
            int row = m0 + wm0 + 16 * mi + g;
            int col = n0 + wn0 + 8 * nj + 2 * c;
            float* d0 = g_part + ((size_t)blockIdx.z * 512 + row) * 512 + col;
            float* d1 = g_part + ((size_t)blockIdx.z * 512 + row + 8) * 512 + col;
            *(float2*)d0 = make_float2(acc[mi][nj][0], acc[mi][nj][1]);
            *(float2*)d1 = make_float2(acc[mi][nj][2], acc[mi][nj][3]);
        }
}
#undef STAGE_A
#undef ISSUE_B

// ---------------- kernel 4: reduce split-K partials + bias + relu ----------
__global__ void reduce_relu_kernel(const float* __restrict__ pb0) {
    int b = blockIdx.x;
    for (int j = threadIdx.x; j < 512; j += 256) {
        float s = pb0[j];
        #pragma unroll
        for (int sp = 0; sp < 18; sp++)
            s += g_part[((size_t)sp * 512 + b) * 512 + j];
        g_h1[(size_t)b * 512 + j] = fmaxf(s, 0.f);
    }
}

// ---------------- kernel 5: prediction MLP + sigmoid -----------------------
__global__ void pred_kernel(const float* __restrict__ pw1, const float* __restrict__ pb1,
                            const float* __restrict__ pw2, const float* __restrict__ pb2,
                            float* __restrict__ out) {
    __shared__ float h1s[4][512];
    __shared__ float h2s[4][256];
    __shared__ float red[4][8];
    const int r0 = blockIdx.x * 4;
    const int tid = threadIdx.x;

    for (int i = tid; i < 2048; i += 256)
        h1s[i >> 9][i & 511] = g_h1[(size_t)(r0 + (i >> 9)) * 512 + (i & 511)];
    __syncthreads();

    {
        float a[4];
        float b = pb1[tid];
        #pragma unroll
        for (int r = 0; r < 4; r++) a[r] = b;
        #pragma unroll 8
        for (int i = 0; i < 512; i++) {
            float w = pw1[i * 256 + tid];
            #pragma unroll
            for (int r = 0; r < 4; r++) a[r] += h1s[r][i] * w;
        }
        #pragma unroll
        for (int r = 0; r < 4; r++) h2s[r][tid] = fmaxf(a[r], 0.f);
    }
    __syncthreads();

    float w2 = pw2[tid];
    int lane = tid & 31, wp = tid >> 5;
    #pragma unroll
    for (int r = 0; r < 4; r++) {
        float v = h2s[r][tid] * w2;
        #pragma unroll
        for (int o = 16; o; o >>= 1) v += __shfl_xor_sync(0xffffffffu, v, o);
        if (lane == 0) red[r][wp] = v;
    }
    __syncthreads();
    if (tid < 4) {
        float s = pb2[0];
        #pragma unroll
        for (int w = 0; w < 8; w++) s += red[tid][w];
        out[r0 + tid] = 1.f / (1.f + expf(-s));
    }
}

// ---------------- launch ----------------------------------------------------
extern "C" void kernel_launch(void* const* d_in, const int* in_sizes, int n_in,
                              void* d_out, int out_size) {
    const float* x   = (const float*)d_in[0];
    const void*  sp  = d_in[1];
    const float* emb = (const float*)d_in[2];
    const float* dw0 = (const float*)d_in[3];
    const float* db0 = (const float*)d_in[4];
    const float* dw1 = (const float*)d_in[5];
    const float* db1 = (const float*)d_in[6];
    const float* dw2 = (const float*)d_in[7];
    const float* db2 = (const float*)d_in[8];
    const float* dw3 = (const float*)d_in[9];
    const float* db3 = (const float*)d_in[10];
    const float* pw0 = (const float*)d_in[11];
    const float* pb0 = (const float*)d_in[12];
    const float* pw1 = (const float*)d_in[13];
    const float* pb1 = (const float*)d_in[14];
    const float* pw2 = (const float*)d_in[15];
    const float* pb2 = (const float*)d_in[16];
    float* out = (float*)d_out;

    cudaFuncSetAttribute(inter_gemm_kernel,
                         cudaFuncAttributeMaxDynamicSharedMemorySize, (int)GSMEM);

    convert_w0_kernel<<<dim3(186624 / 64, 8), 256>>>(pw0);
    dense_mlp_kernel<<<128, 256>>>(x, dw0, db0, dw1, db1, dw2, db2, dw3, db3);
    embed_kernel<<<52, 256>>>(sp, emb);
    inter_gemm_kernel<<<dim3(4, 4, 18), 256, GSMEM>>>();
    reduce_relu_kernel<<<512, 256>>>(pb0);
    pred_kernel<<<128, 256>>>(pw1, pb1, pw2, pb2, out);
}